// round 12
// baseline (speedup 1.0000x reference)
#include <cuda_runtime.h>
#include <cuda_bf16.h>
#include <cstdint>
#include <math.h>

#define BSZ   128
#define GSZ   2000
#define EF    128
#define KM    4
#define NEGV  (-1e30f)
#define GT    64
#define WP    68            // smem pitch in 32-bit words (136 bf16), 68 % 32 == 4
#define BB    4

// ---------------- static device scratch --------------------------------------
struct Scal {
    int act[KM];
    int idxq1[KM];
    int idxq2[KM];
    int vtt_a[KM];
    int stopped[KM];
    int allow[KM];
    int vt0;
    int last_action;
    int ai0;
};
__device__ Scal  g_scal[BSZ];
__device__ float g_hmean[BSZ * EF];
__device__ float g_WQ[BSZ * KM * 4 * EF];                 // [b][it][m][f]
__device__ float g_L[(size_t)BSZ * KM * GSZ];             // masked logits

// ---------------- helpers ----------------------------------------------------
__device__ __forceinline__ float tanha(float x) {
    float r; asm("tanh.approx.f32 %0, %1;" : "=f"(r) : "f"(x)); return r;
}
__device__ __forceinline__ uint32_t packbf(float lo, float hi) {
    uint32_t r;
    asm("cvt.rn.bf16x2.f32 %0, %1, %2;" : "=r"(r) : "f"(hi), "f"(lo));
    return r;
}
__device__ __forceinline__ void mma_bf16(float* c, uint32_t a0, uint32_t a1,
                                         uint32_t a2, uint32_t a3,
                                         uint32_t b0, uint32_t b1) {
    asm volatile("mma.sync.aligned.m16n8k16.row.col.f32.bf16.bf16.f32 "
                 "{%0,%1,%2,%3},{%4,%5,%6,%7},{%8,%9},{%0,%1,%2,%3};"
                 : "+f"(c[0]), "+f"(c[1]), "+f"(c[2]), "+f"(c[3])
                 : "r"(a0), "r"(a1), "r"(a2), "r"(a3), "r"(b0), "r"(b1));
}
#define LDSM4(r0, r1, r2, r3, addr)                                            \
    asm volatile("ldmatrix.sync.aligned.m8n8.x4.shared.b16 {%0,%1,%2,%3}, [%4];" \
                 : "=r"(r0), "=r"(r1), "=r"(r2), "=r"(r3) : "r"(addr))
__device__ __forceinline__ float sigm(float x) { return 1.0f / (1.0f + expf(-x)); }
__device__ __forceinline__ int modg(int x) { int r = x % GSZ; return (r < 0) ? r + GSZ : r; }

// ---------------- kernel A: integer trajectory + action_all -------------------
__global__ void kA(const int* __restrict__ rec, const int* __restrict__ vt,
                   const int* __restrict__ last_action, const int* __restrict__ fixed_action,
                   float* __restrict__ out) {
    int b = threadIdx.x;
    if (b >= BSZ) return;
    int ai[KM] = {0, 0, 0, 0}, kl[KM + 1] = {0, 0, 0, 0, 0}, kr[KM] = {0, 0, 0, 0};
    bool stopped = true;
    int nol = -1, vt0 = 0;
    Scal s;
    for (int i = 0; i < KM; i++) {
        int act = fixed_action[b * KM + i];
        if (i > 0 && stopped) act = ai[0];
        int nna = rec[b * GSZ + act];
        ai[i] = act;
        if (stopped)  kl[i] = act;
        if (!stopped) kr[(i + KM - 1) % KM] = act;
        kl[i + 1] = nna;
        s.idxq1[i] = act;
        s.idxq2[i] = stopped ? act : modg(nol);
        bool eq = (act == nol);
        stopped = (i == 0) ? eq : (stopped || eq);
        if (stopped) kl[i] = kl[(i + KM) % (KM + 1)];
        if (stopped) kr[i] = kr[(i + KM - 1) % KM];
        if (i == 0) vt0 = vt[b * GSZ + act];
        s.vtt_a[i]   = modg(vt[b * GSZ + act] - vt0);
        s.stopped[i] = stopped ? 1 : 0;
        s.act[i]     = act;
        s.allow[i]   = (!stopped && (nna == ai[0])) ? 1 : 0;
        nol = stopped ? -1 : nna;
    }
    if (!stopped) kr[KM - 1] = kl[KM];
    s.vt0 = vt0;
    s.last_action = last_action[b];
    s.ai0 = ai[0];
    g_scal[b] = s;
    for (int j = 0; j < KM; j++) {
        out[b * 12 + j]     = (float)ai[j];
        out[b * 12 + 4 + j] = (float)kl[j];
        out[b * 12 + 8 + j] = (float)kr[j];
    }
}

// ---------------- kernel B0: hmean --------------------------------------------
__global__ void kB0(const float* __restrict__ h) {
    int b = blockIdx.y;
    int tid = threadIdx.x;
    int lane = tid & 31, slice = tid >> 5;
    int e = blockIdx.x * 32 + lane;
    float acc = 0.f;
    for (int g = slice; g < GSZ; g += 8)
        acc += h[((size_t)b * GSZ + g) * EF + e];
    __shared__ float red[256];
    red[tid] = acc;
    __syncthreads();
    for (int st = 128; st >= 32; st >>= 1) {
        if (tid < st) red[tid] += red[tid + st];
        __syncthreads();
    }
    if (tid < 32) g_hmean[b * EF + blockIdx.x * 32 + tid] = red[tid] * (1.0f / (float)GSZ);
}

// ---------------- kernel B: GRU recurrence + W_Q projections (BB batched) -----
__global__ void __launch_bounds__(512) kB(
    const float* __restrict__ h,
    const float* __restrict__ W_init, const float* __restrict__ b_init,
    const float* __restrict__ init_q,
    const float* __restrict__ W1ih, const float* __restrict__ W1hh,
    const float* __restrict__ b1ih, const float* __restrict__ b1hh,
    const float* __restrict__ W2ih, const float* __restrict__ W2hh,
    const float* __restrict__ b2ih, const float* __restrict__ b2hh,
    const float* __restrict__ WQ1, const float* __restrict__ WQ2,
    const float* __restrict__ WQ3, const float* __restrict__ WQ4) {
    int b0 = blockIdx.x * BB;
    int tid = threadIdx.x;
    __shared__ __align__(16) float x1[BB][EF], x2[BB][EF], q1[BB][EF], q2[BB][EF];
    __shared__ __align__(16) float gg[4][BB][3 * EF];

    { int lb = tid >> 7, e = tid & 127; x1[lb][e] = g_hmean[(b0 + lb) * EF + e]; }
    __syncthreads();
    if (tid < EF) {
        float bi = b_init[tid];
        float s[BB];
#pragma unroll
        for (int lb = 0; lb < BB; lb++) s[lb] = bi;
        const float4* w = (const float4*)(W_init + tid * EF);
#pragma unroll 8
        for (int k = 0; k < 32; k++) {
            float4 a = __ldg(&w[k]);
#pragma unroll
            for (int lb = 0; lb < BB; lb++) {
                float4 c = ((const float4*)x1[lb])[k];
                s[lb] += a.x * c.x + a.y * c.y + a.z * c.z + a.w * c.w;
            }
        }
#pragma unroll
        for (int lb = 0; lb < BB; lb++) { q1[lb][tid] = s[lb]; q2[lb][tid] = s[lb]; }
    }
    __syncthreads();

    for (int it = 0; it < KM; it++) {
        {
            int lb = tid >> 7, e = tid & 127;
            if (it == 0) { float v = init_q[e]; x1[lb][e] = v; x2[lb][e] = v; }
            else {
                const Scal* sc = &g_scal[b0 + lb];
                x1[lb][e] = h[((size_t)(b0 + lb) * GSZ + sc->idxq1[it - 1]) * EF + e];
                x2[lb][e] = h[((size_t)(b0 + lb) * GSZ + sc->idxq2[it - 1]) * EF + e];
            }
        }
        __syncthreads();

        for (int row = tid; row < 1536; row += 512) {
            int task = row / 384, r = row % 384;
            const float* W; const float (*src)[EF];
            if (task == 0)      { W = W1ih; src = x1; }
            else if (task == 1) { W = W1hh; src = q1; }
            else if (task == 2) { W = W2ih; src = x2; }
            else                { W = W2hh; src = q2; }
            const float4* w = (const float4*)(W + r * EF);
            float s[BB];
#pragma unroll
            for (int lb = 0; lb < BB; lb++) s[lb] = 0.f;
#pragma unroll 4
            for (int k = 0; k < 32; k++) {
                float4 a = __ldg(&w[k]);
#pragma unroll
                for (int lb = 0; lb < BB; lb++) {
                    float4 c = ((const float4*)src[lb])[k];
                    s[lb] += a.x * c.x + a.y * c.y + a.z * c.z + a.w * c.w;
                }
            }
#pragma unroll
            for (int lb = 0; lb < BB; lb++) gg[task][lb][r] = s[lb];
        }
        __syncthreads();

        {
            int lb = tid >> 7, f = tid & 127;
            float r1 = sigm(gg[0][lb][f] + b1ih[f] + gg[1][lb][f] + b1hh[f]);
            float z1 = sigm(gg[0][lb][EF + f] + b1ih[EF + f] + gg[1][lb][EF + f] + b1hh[EF + f]);
            float n1 = tanhf(gg[0][lb][2 * EF + f] + b1ih[2 * EF + f] + r1 * (gg[1][lb][2 * EF + f] + b1hh[2 * EF + f]));
            q1[lb][f] = (1.f - z1) * n1 + z1 * q1[lb][f];
            float r2 = sigm(gg[2][lb][f] + b2ih[f] + gg[3][lb][f] + b2hh[f]);
            float z2 = sigm(gg[2][lb][EF + f] + b2ih[EF + f] + gg[3][lb][EF + f] + b2hh[EF + f]);
            float n2 = tanhf(gg[2][lb][2 * EF + f] + b2ih[2 * EF + f] + r2 * (gg[3][lb][2 * EF + f] + b2hh[2 * EF + f]));
            q2[lb][f] = (1.f - z2) * n2 + z2 * q2[lb][f];
        }
        __syncthreads();

        {
            int m = tid >> 7, r = tid & 127;
            const float* W = (m == 0) ? WQ1 : (m == 1) ? WQ2 : (m == 2) ? WQ3 : WQ4;
            const float (*src)[EF] = (m == 0 || m == 2) ? q1 : q2;
            const float4* w = (const float4*)(W + r * EF);
            float s[BB];
#pragma unroll
            for (int lb = 0; lb < BB; lb++) s[lb] = 0.f;
#pragma unroll 4
            for (int k = 0; k < 32; k++) {
                float4 a = __ldg(&w[k]);
#pragma unroll
                for (int lb = 0; lb < BB; lb++) {
                    float4 c = ((const float4*)src[lb])[k];
                    s[lb] += a.x * c.x + a.y * c.y + a.z * c.z + a.w * c.w;
                }
            }
#pragma unroll
            for (int lb = 0; lb < BB; lb++)
                g_WQ[(((b0 + lb) * KM + it) * 4 + m) * EF + r] = s[lb];
        }
        __syncthreads();
    }
}

// ---------------- kernel C: bf16 tensor-core K*h + fused scores ---------------
#define SMW_H   (GT * WP)            // 4352
#define SMW_W   (2 * EF * WP)        // 17408
#define SMW_WQ  2048
#define SMW_V   256
#define SMW_SS  (2 * 4 * GT * 4)     // 2048
#define KC_SMEM ((SMW_H + SMW_W + SMW_WQ + SMW_V + SMW_SS) * 4)

__global__ void __launch_bounds__(512, 2) kC(
    const float* __restrict__ h, const int* __restrict__ vt,
    const float* __restrict__ Wk1, const float* __restrict__ Wk2,
    const float* __restrict__ Wk3, const float* __restrict__ Wk4,
    const float* __restrict__ V1, const float* __restrict__ V2) {
    int tile = blockIdx.x, b = blockIdx.y;
    int g0 = tile * GT;
    int tid = threadIdx.x, lane = tid & 31, warp = tid >> 5;
    int gt = warp & 3;           // g-tile (16 rows each)
    int fq = warp >> 2;          // f-quarter (32 cols each)
    int r  = lane >> 2;          // 0..7
    int cc = lane & 3;           // 0..3

    extern __shared__ float smf[];
    uint32_t* shb = (uint32_t*)smf;          // h tile, bf16x2 words
    uint32_t* sWb = shb + SMW_H;             // two W matrices, bf16x2 words
    float*    swq = (float*)(sWb + SMW_W);
    float*    sv  = swq + SMW_WQ;
    float*    ss  = sv + SMW_V;              // [pass][fq][g][it]
    __shared__ int  svt[GT];
    __shared__ Scal sS;

    // ---- stage h tile (convert to bf16) ----
    for (int idx = tid; idx < (GT * EF) / 4; idx += 512) {
        int el = idx * 4;
        int g = el >> 7, e = el & 127;
        float4 v = make_float4(0.f, 0.f, 0.f, 0.f);
        if (g0 + g < GSZ) v = *(const float4*)(h + ((size_t)b * GSZ + g0 + g) * EF + e);
        uint2 w;
        w.x = packbf(v.x, v.y);
        w.y = packbf(v.z, v.w);
        *(uint2*)(shb + g * WP + (e >> 1)) = w;
    }
    for (int idx = tid; idx < SMW_WQ; idx += 512) swq[idx] = g_WQ[b * SMW_WQ + idx];
    if (tid < EF) { sv[tid] = V1[tid]; sv[EF + tid] = V2[tid]; }
    if (tid == 0) sS = g_scal[b];
    __syncthreads();
    if (tid < GT) {
        int gg = g0 + tid;
        svt[tid] = (gg < GSZ) ? modg(vt[b * GSZ + gg] - sS.vt0) : 0;
    }

    // ---- ldmatrix base addresses (byte addresses in shared space) ----
    // A frags: row = gt*16 + (lane & 15), word +4 if lane >= 16
    uint32_t aBase;
    {
        int mrow = gt * 16 + (lane & 15);
        int woff = (lane & 16) ? 4 : 0;
        aBase = (uint32_t)__cvta_generic_to_shared(shb + mrow * WP + woff);
    }
    // B frags: row = fq*32 + p*16 + ((lane&16)?8:0) + (lane&7), word +4 if lane&8
    uint32_t bBase0;
    {
        int nrow = fq * 32 + ((lane & 16) >> 1) + (lane & 7);
        int woff = (lane & 8) ? 4 : 0;
        bBase0 = (uint32_t)__cvta_generic_to_shared(sWb + nrow * WP + woff);
    }
    const uint32_t P16 = 16 * WP * 4;        // 16 rows in bytes
    const uint32_t MOFF = EF * WP * 4;       // second matrix offset in bytes

#pragma unroll 1
    for (int pass = 0; pass < 2; pass++) {
        const float* WA = pass ? Wk2 : Wk1;   // additive K-matrix
        const float* WB = pass ? Wk4 : Wk3;   // multiplicative K-matrix
        __syncthreads();
        // ---- stage W pair (convert to bf16) ----
        for (int idx = tid; idx < (EF * EF) / 4; idx += 512) {
            int el = idx * 4;
            int f = el >> 7, k = el & 127;
            float4 wa = *(const float4*)(WA + f * EF + k);
            float4 wb = *(const float4*)(WB + f * EF + k);
            uint2 pa, pb;
            pa.x = packbf(wa.x, wa.y); pa.y = packbf(wa.z, wa.w);
            pb.x = packbf(wb.x, wb.y); pb.y = packbf(wb.z, wb.w);
            *(uint2*)(sWb + f * WP + (k >> 1)) = pa;
            *(uint2*)(sWb + EF * WP + f * WP + (k >> 1)) = pb;
        }
        __syncthreads();

        // ---- GEMM via ldmatrix + m16n8k16 ----
        float accA[4][4], accB[4][4];
#pragma unroll
        for (int nt = 0; nt < 4; nt++)
#pragma unroll
            for (int j = 0; j < 4; j++) { accA[nt][j] = 0.f; accB[nt][j] = 0.f; }

#pragma unroll
        for (int ks = 0; ks < 8; ks++) {
            uint32_t koff = ks * 32;          // 8 words = 32 bytes per k-step
            uint32_t a0, a1, a2, a3;
            LDSM4(a0, a1, a2, a3, aBase + koff);
            uint32_t A00, A01, A10, A11;      // WA: {b0_nt0,b1_nt0,b0_nt1,b1_nt1}
            LDSM4(A00, A01, A10, A11, bBase0 + koff);
            uint32_t A20, A21, A30, A31;      // WA p=1: nt2, nt3
            LDSM4(A20, A21, A30, A31, bBase0 + P16 + koff);
            uint32_t B00, B01, B10, B11;      // WB p=0
            LDSM4(B00, B01, B10, B11, bBase0 + MOFF + koff);
            uint32_t B20, B21, B30, B31;      // WB p=1
            LDSM4(B20, B21, B30, B31, bBase0 + MOFF + P16 + koff);
            mma_bf16(accA[0], a0, a1, a2, a3, A00, A01);
            mma_bf16(accA[1], a0, a1, a2, a3, A10, A11);
            mma_bf16(accA[2], a0, a1, a2, a3, A20, A21);
            mma_bf16(accA[3], a0, a1, a2, a3, A30, A31);
            mma_bf16(accB[0], a0, a1, a2, a3, B00, B01);
            mma_bf16(accB[1], a0, a1, a2, a3, B10, B11);
            mma_bf16(accB[2], a0, a1, a2, a3, B20, B21);
            mma_bf16(accB[3], a0, a1, a2, a3, B30, B31);
        }

        // ---- score phase on fragments (vectorized shared loads) ----
        int mA = pass ? 1 : 0;
        int mM = pass ? 3 : 2;
        float sacc[2][4];
#pragma unroll
        for (int row = 0; row < 2; row++)
#pragma unroll
            for (int it = 0; it < 4; it++) sacc[row][it] = 0.f;

#pragma unroll
        for (int nt = 0; nt < 4; nt++) {
            int c0 = fq * 32 + nt * 8 + 2 * cc;
            float2 v01 = *(const float2*)(sv + pass * EF + c0);
#pragma unroll
            for (int it = 0; it < 4; it++) {
                float2 wA = *(const float2*)(swq + it * 512 + mA * EF + c0);
                float2 wM = *(const float2*)(swq + it * 512 + mM * EF + c0);
                sacc[0][it] += v01.x * tanha(accA[nt][0] + wA.x + accB[nt][0] * wM.x)
                             + v01.y * tanha(accA[nt][1] + wA.y + accB[nt][1] * wM.y);
                sacc[1][it] += v01.x * tanha(accA[nt][2] + wA.x + accB[nt][2] * wM.x)
                             + v01.y * tanha(accA[nt][3] + wA.y + accB[nt][3] * wM.y);
            }
        }
#pragma unroll
        for (int row = 0; row < 2; row++)
#pragma unroll
            for (int it = 0; it < 4; it++) {
                float x = sacc[row][it];
                x += __shfl_xor_sync(0xffffffffu, x, 1);
                x += __shfl_xor_sync(0xffffffffu, x, 2);
                if (cc == 0) {
                    int g = gt * 16 + r + row * 8;
                    ss[((pass * 4 + fq) * GT + g) * 4 + it] = x;
                }
            }
    }
    __syncthreads();

    // ---- combine, mask, write logits ----
    if (tid < GT * 4) {
        int g = tid >> 2, it = tid & 3;
        float s = 0.f;
#pragma unroll
        for (int j = 0; j < 8; j++) s += ss[(j * GT + g) * 4 + it];
        int gg = g0 + g;
        if (gg < GSZ) {
            bool msk;
            if (it == 0) msk = (gg == sS.last_action);
            else {
                int j = it - 1;
                int d = svt[g];
                msk = (d <= sS.vtt_a[j]);
                if (j == 0) msk = msk || (d > GSZ - 2);
                if (sS.stopped[j] && gg == sS.act[j]) msk = false;
                if (sS.allow[j] && gg == sS.ai0) msk = false;
            }
            g_L[((size_t)(b * KM + it)) * GSZ + gg] = msk ? NEGV : tanhf(s) * 10.0f;
        }
    }
}

// ---------------- kernel D: log-softmax + ll ----------------------------------
__global__ void kD(float* __restrict__ out) {
    int b = blockIdx.x;
    int tid = threadIdx.x;
    __shared__ float red[256];
    __shared__ Scal sS;
    if (tid == 0) sS = g_scal[b];
    __syncthreads();
    float ll = 0.f;
    for (int it = 0; it < KM; it++) {
        const float* Lp = g_L + ((size_t)(b * KM + it)) * GSZ;
        float mx = -3.4e38f;
        for (int gi = tid; gi < GSZ; gi += 256) mx = fmaxf(mx, Lp[gi]);
        red[tid] = mx;
        __syncthreads();
        for (int st = 128; st >= 1; st >>= 1) {
            if (tid < st) red[tid] = fmaxf(red[tid], red[tid + st]);
            __syncthreads();
        }
        mx = red[0];
        __syncthreads();
        float se = 0.f;
        for (int gi = tid; gi < GSZ; gi += 256) se += expf(Lp[gi] - mx);
        red[tid] = se;
        __syncthreads();
        for (int st = 128; st >= 1; st >>= 1) {
            if (tid < st) red[tid] += red[tid + st];
            __syncthreads();
        }
        if (tid == 0) {
            float lse = mx + logf(red[0]);
            float loss = Lp[sS.act[it]] - lse;
            if (it == 0) ll += loss;
            else if (!sS.stopped[it - 1]) ll += loss;
        }
        __syncthreads();
    }
    if (tid == 0) out[BSZ * 12 + b] = ll;
}

// ---------------- launch ------------------------------------------------------
extern "C" void kernel_launch(void* const* d_in, const int* in_sizes, int n_in,
                              void* d_out, int out_size) {
    const float* h   = (const float*)d_in[0];
    const int*   rec = (const int*)d_in[1];
    const int*   vt  = (const int*)d_in[3];
    const int*   la  = (const int*)d_in[4];
    const int*   fa  = (const int*)d_in[5];
    const float* Wk1 = (const float*)d_in[6];
    const float* Wk2 = (const float*)d_in[7];
    const float* Wk3 = (const float*)d_in[8];
    const float* Wk4 = (const float*)d_in[9];
    const float* WQ1 = (const float*)d_in[10];
    const float* WQ2 = (const float*)d_in[11];
    const float* WQ3 = (const float*)d_in[12];
    const float* WQ4 = (const float*)d_in[13];

    const float *Winit, *binit, *V1, *V2, *initq;
    int base;
    if (in_sizes[14] == EF * EF) {
        Winit = (const float*)d_in[14];
        binit = (const float*)d_in[15];
        V1    = (const float*)d_in[16];
        V2    = (const float*)d_in[17];
        initq = (const float*)d_in[18];
        base = 19;
    } else {
        V1    = (const float*)d_in[14];
        V2    = (const float*)d_in[15];
        Winit = (const float*)d_in[16];
        binit = (const float*)d_in[17];
        initq = (const float*)d_in[18];
        base = 19;
    }
    const float* W1ih = (const float*)d_in[base + 0];
    const float* W1hh = (const float*)d_in[base + 1];
    const float* b1ih = (const float*)d_in[base + 2];
    const float* b1hh = (const float*)d_in[base + 3];
    const float* W2ih = (const float*)d_in[base + 4];
    const float* W2hh = (const float*)d_in[base + 5];
    const float* b2ih = (const float*)d_in[base + 6];
    const float* b2hh = (const float*)d_in[base + 7];

    float* out = (float*)d_out;

    cudaFuncSetAttribute(kC, cudaFuncAttributeMaxDynamicSharedMemorySize, KC_SMEM);

    kA<<<1, 128>>>(rec, vt, la, fa, out);
    kB0<<<dim3(4, BSZ), 256>>>(h);
    kB<<<BSZ / BB, 512>>>(h, Winit, binit, initq,
                          W1ih, W1hh, b1ih, b1hh, W2ih, W2hh, b2ih, b2hh,
                          WQ1, WQ2, WQ3, WQ4);
    kC<<<dim3((GSZ + GT - 1) / GT, BSZ), 512, KC_SMEM>>>(h, vt, Wk1, Wk2, Wk3, Wk4, V1, V2);
    kD<<<BSZ, 256>>>(out);
}

// round 13
// speedup vs baseline: 1.7517x; 1.7517x over previous
#include <cuda_runtime.h>
#include <cuda_bf16.h>
#include <cstdint>
#include <math.h>

#define BSZ   128
#define GSZ   2000
#define EF    128
#define KM    4
#define NEGV  (-1e30f)
#define GT    64
#define WP    68            // smem pitch in 32-bit words (136 bf16), 68 % 32 == 4

#define SMW_H   (GT * WP)            // 4352
#define SMW_W   (2 * EF * WP)        // 17408
#define SMW_WQ  2048
#define SMW_V   256
#define SMW_SS  (2 * 4 * GT * 4)     // 2048
#define KC_SMEM ((SMW_H + SMW_W + SMW_WQ + SMW_V + SMW_SS) * 4)

// ---------------- static device scratch --------------------------------------
struct Scal {
    int act[KM];
    int idxq1[KM];
    int idxq2[KM];
    int vtt_a[KM];
    int stopped[KM];
    int allow[KM];
    int vt0;
    int last_action;
    int ai0;
};
__device__ Scal  g_scal[BSZ];
__device__ float g_hmean[BSZ * EF];
__device__ float g_WQ[BSZ * KM * 4 * EF];                 // [b][it][m][f]
__device__ float g_L[(size_t)BSZ * KM * GSZ];             // masked logits
__device__ uint32_t g_Wb[2 * SMW_W];                      // bf16 W, smem layout per pass

// ---------------- helpers ----------------------------------------------------
__device__ __forceinline__ float tanha(float x) {
    float r; asm("tanh.approx.f32 %0, %1;" : "=f"(r) : "f"(x)); return r;
}
__device__ __forceinline__ uint32_t packbf(float lo, float hi) {
    uint32_t r;
    asm("cvt.rn.bf16x2.f32 %0, %1, %2;" : "=r"(r) : "f"(hi), "f"(lo));
    return r;
}
__device__ __forceinline__ void mma_bf16(float* c, uint32_t a0, uint32_t a1,
                                         uint32_t a2, uint32_t a3,
                                         uint32_t b0, uint32_t b1) {
    asm volatile("mma.sync.aligned.m16n8k16.row.col.f32.bf16.bf16.f32 "
                 "{%0,%1,%2,%3},{%4,%5,%6,%7},{%8,%9},{%0,%1,%2,%3};"
                 : "+f"(c[0]), "+f"(c[1]), "+f"(c[2]), "+f"(c[3])
                 : "r"(a0), "r"(a1), "r"(a2), "r"(a3), "r"(b0), "r"(b1));
}
__device__ __forceinline__ float sigm(float x) { return 1.0f / (1.0f + expf(-x)); }
__device__ __forceinline__ int modg(int x) { int r = x % GSZ; return (r < 0) ? r + GSZ : r; }

// ---------------- kernel A: integer trajectory + action_all -------------------
__global__ void kA(const int* __restrict__ rec, const int* __restrict__ vt,
                   const int* __restrict__ last_action, const int* __restrict__ fixed_action,
                   float* __restrict__ out) {
    int b = threadIdx.x;
    if (b >= BSZ) return;
    int ai[KM] = {0, 0, 0, 0}, kl[KM + 1] = {0, 0, 0, 0, 0}, kr[KM] = {0, 0, 0, 0};
    bool stopped = true;
    int nol = -1, vt0 = 0;
    Scal s;
    for (int i = 0; i < KM; i++) {
        int act = fixed_action[b * KM + i];
        if (i > 0 && stopped) act = ai[0];
        int nna = rec[b * GSZ + act];
        ai[i] = act;
        if (stopped)  kl[i] = act;
        if (!stopped) kr[(i + KM - 1) % KM] = act;
        kl[i + 1] = nna;
        s.idxq1[i] = act;
        s.idxq2[i] = stopped ? act : modg(nol);
        bool eq = (act == nol);
        stopped = (i == 0) ? eq : (stopped || eq);
        if (stopped) kl[i] = kl[(i + KM) % (KM + 1)];
        if (stopped) kr[i] = kr[(i + KM - 1) % KM];
        if (i == 0) vt0 = vt[b * GSZ + act];
        s.vtt_a[i]   = modg(vt[b * GSZ + act] - vt0);
        s.stopped[i] = stopped ? 1 : 0;
        s.act[i]     = act;
        s.allow[i]   = (!stopped && (nna == ai[0])) ? 1 : 0;
        nol = stopped ? -1 : nna;
    }
    if (!stopped) kr[KM - 1] = kl[KM];
    s.vt0 = vt0;
    s.last_action = last_action[b];
    s.ai0 = ai[0];
    g_scal[b] = s;
    for (int j = 0; j < KM; j++) {
        out[b * 12 + j]     = (float)ai[j];
        out[b * 12 + 4 + j] = (float)kl[j];
        out[b * 12 + 8 + j] = (float)kr[j];
    }
}

// ---------------- kernel Pw: one-time W -> bf16 (padded smem layout) ----------
__global__ void kPw(const float* __restrict__ Wk1, const float* __restrict__ Wk2,
                    const float* __restrict__ Wk3, const float* __restrict__ Wk4) {
    int pass = blockIdx.x;
    const float* WA = pass ? Wk2 : Wk1;
    const float* WB = pass ? Wk4 : Wk3;
    uint32_t* dst = g_Wb + pass * SMW_W;
    int tid = threadIdx.x;
    for (int idx = tid; idx < (EF * EF) / 4; idx += 512) {
        int el = idx * 4;
        int f = el >> 7, k = el & 127;
        float4 wa = *(const float4*)(WA + f * EF + k);
        float4 wb = *(const float4*)(WB + f * EF + k);
        uint2 pa, pb;
        pa.x = packbf(wa.x, wa.y); pa.y = packbf(wa.z, wa.w);
        pb.x = packbf(wb.x, wb.y); pb.y = packbf(wb.z, wb.w);
        *(uint2*)(dst + f * WP + (k >> 1)) = pa;
        *(uint2*)(dst + EF * WP + f * WP + (k >> 1)) = pb;
    }
}

// ---------------- kernel B0: hmean --------------------------------------------
__global__ void kB0(const float* __restrict__ h) {
    int b = blockIdx.y;
    int tid = threadIdx.x;
    int lane = tid & 31, slice = tid >> 5;
    int e = blockIdx.x * 32 + lane;
    float acc = 0.f;
    for (int g = slice; g < GSZ; g += 8)
        acc += h[((size_t)b * GSZ + g) * EF + e];
    __shared__ float red[256];
    red[tid] = acc;
    __syncthreads();
    for (int st = 128; st >= 32; st >>= 1) {
        if (tid < st) red[tid] += red[tid + st];
        __syncthreads();
    }
    if (tid < 32) g_hmean[b * EF + blockIdx.x * 32 + tid] = red[tid] * (1.0f / (float)GSZ);
}

// ---------------- kernel B: GRU recurrence + W_Q projections ------------------
__global__ void __launch_bounds__(512) kB(
    const float* __restrict__ h,
    const float* __restrict__ W_init, const float* __restrict__ b_init,
    const float* __restrict__ init_q,
    const float* __restrict__ W1ih, const float* __restrict__ W1hh,
    const float* __restrict__ b1ih, const float* __restrict__ b1hh,
    const float* __restrict__ W2ih, const float* __restrict__ W2hh,
    const float* __restrict__ b2ih, const float* __restrict__ b2hh,
    const float* __restrict__ WQ1, const float* __restrict__ WQ2,
    const float* __restrict__ WQ3, const float* __restrict__ WQ4) {
    int b = blockIdx.x;
    int tid = threadIdx.x;
    __shared__ __align__(16) float x1[EF], x2[EF], q1[EF], q2[EF];
    __shared__ __align__(16) float gg[4][3 * EF];

    if (tid < EF) x1[tid] = g_hmean[b * EF + tid];
    __syncthreads();
    if (tid < EF) {
        float s = b_init[tid];
        const float4* w = (const float4*)(W_init + tid * EF);
        const float4* xv = (const float4*)x1;
#pragma unroll 8
        for (int k = 0; k < 32; k++) {
            float4 a = w[k], c = xv[k];
            s += a.x * c.x + a.y * c.y + a.z * c.z + a.w * c.w;
        }
        q1[tid] = s; q2[tid] = s;
    }
    __syncthreads();

    for (int it = 0; it < KM; it++) {
        if (tid < EF) {
            if (it == 0) { float v = init_q[tid]; x1[tid] = v; x2[tid] = v; }
            else {
                const Scal* sc = &g_scal[b];
                x1[tid] = h[((size_t)b * GSZ + sc->idxq1[it - 1]) * EF + tid];
                x2[tid] = h[((size_t)b * GSZ + sc->idxq2[it - 1]) * EF + tid];
            }
        }
        __syncthreads();

        for (int row = tid; row < 1536; row += 512) {
            int task = row / 384, r = row % 384;
            const float* W; const float* src;
            if (task == 0)      { W = W1ih; src = x1; }
            else if (task == 1) { W = W1hh; src = q1; }
            else if (task == 2) { W = W2ih; src = x2; }
            else                { W = W2hh; src = q2; }
            const float4* w = (const float4*)(W + r * EF);
            const float4* xv = (const float4*)src;
            float s = 0.f;
#pragma unroll 8
            for (int k = 0; k < 32; k++) {
                float4 a = __ldg(&w[k]); float4 c = xv[k];
                s += a.x * c.x + a.y * c.y + a.z * c.z + a.w * c.w;
            }
            gg[task][r] = s;
        }
        __syncthreads();

        if (tid < EF) {
            int f = tid;
            float r1 = sigm(gg[0][f] + b1ih[f] + gg[1][f] + b1hh[f]);
            float z1 = sigm(gg[0][EF + f] + b1ih[EF + f] + gg[1][EF + f] + b1hh[EF + f]);
            float n1 = tanhf(gg[0][2 * EF + f] + b1ih[2 * EF + f] + r1 * (gg[1][2 * EF + f] + b1hh[2 * EF + f]));
            q1[f] = (1.f - z1) * n1 + z1 * q1[f];
            float r2 = sigm(gg[2][f] + b2ih[f] + gg[3][f] + b2hh[f]);
            float z2 = sigm(gg[2][EF + f] + b2ih[EF + f] + gg[3][EF + f] + b2hh[EF + f]);
            float n2 = tanhf(gg[2][2 * EF + f] + b2ih[2 * EF + f] + r2 * (gg[3][2 * EF + f] + b2hh[2 * EF + f]));
            q2[f] = (1.f - z2) * n2 + z2 * q2[f];
        }
        __syncthreads();

        {
            int m = tid >> 7, r = tid & 127;
            const float* W = (m == 0) ? WQ1 : (m == 1) ? WQ2 : (m == 2) ? WQ3 : WQ4;
            const float* src = (m == 0 || m == 2) ? q1 : q2;
            const float4* w = (const float4*)(W + r * EF);
            const float4* xv = (const float4*)src;
            float s = 0.f;
#pragma unroll 8
            for (int k = 0; k < 32; k++) {
                float4 a = __ldg(&w[k]); float4 c = xv[k];
                s += a.x * c.x + a.y * c.y + a.z * c.z + a.w * c.w;
            }
            g_WQ[((b * KM + it) * 4 + m) * EF + r] = s;
        }
        __syncthreads();
    }
}

// ---------------- kernel C: bf16 tensor-core K*h + fused scores ---------------
__global__ void __launch_bounds__(512, 2) kC(
    const float* __restrict__ h, const int* __restrict__ vt,
    const float* __restrict__ V1, const float* __restrict__ V2) {
    int tile = blockIdx.x, b = blockIdx.y;
    int g0 = tile * GT;
    int tid = threadIdx.x, lane = tid & 31, warp = tid >> 5;
    int gt = warp & 3;           // g-tile (16 rows each)
    int fq = warp >> 2;          // f-quarter (32 cols each)
    int r  = lane >> 2;          // 0..7
    int cc = lane & 3;           // 0..3

    extern __shared__ float smf[];
    uint32_t* shb = (uint32_t*)smf;          // h tile, bf16x2 words
    uint32_t* sWb = shb + SMW_H;             // two W matrices, bf16x2 words
    float*    swq = (float*)(sWb + SMW_W);
    float*    sv  = swq + SMW_WQ;
    float*    ss  = sv + SMW_V;              // [pass][fq][g][it]
    __shared__ int  svt[GT];
    __shared__ Scal sS;

    // ---- stage h tile (convert to bf16) ----
    for (int idx = tid; idx < (GT * EF) / 4; idx += 512) {
        int el = idx * 4;
        int g = el >> 7, e = el & 127;
        float4 v = make_float4(0.f, 0.f, 0.f, 0.f);
        if (g0 + g < GSZ) v = *(const float4*)(h + ((size_t)b * GSZ + g0 + g) * EF + e);
        uint2 w;
        w.x = packbf(v.x, v.y);
        w.y = packbf(v.z, v.w);
        *(uint2*)(shb + g * WP + (e >> 1)) = w;
    }
    for (int idx = tid; idx < SMW_WQ; idx += 512) swq[idx] = g_WQ[b * SMW_WQ + idx];
    if (tid < EF) { sv[tid] = V1[tid]; sv[EF + tid] = V2[tid]; }
    if (tid == 0) sS = g_scal[b];
    __syncthreads();
    if (tid < GT) {
        int gg = g0 + tid;
        svt[tid] = (gg < GSZ) ? modg(vt[b * GSZ + gg] - sS.vt0) : 0;
    }

#pragma unroll 1
    for (int pass = 0; pass < 2; pass++) {
        __syncthreads();
        // ---- stage pre-converted bf16 W pair (plain vector copy) ----
        {
            const uint4* src = (const uint4*)(g_Wb + pass * SMW_W);
            uint4* dst = (uint4*)sWb;
            for (int idx = tid; idx < SMW_W / 4; idx += 512)
                dst[idx] = __ldg(&src[idx]);
        }
        __syncthreads();

        // ---- GEMM: accA = h @ WA^T, accB = h @ WB^T (m16n8k16 bf16) ----
        float accA[4][4], accB[4][4];
#pragma unroll
        for (int nt = 0; nt < 4; nt++)
#pragma unroll
            for (int j = 0; j < 4; j++) { accA[nt][j] = 0.f; accB[nt][j] = 0.f; }

        const uint32_t* pA = shb + (gt * 16 + r) * WP + cc;
        const uint32_t* pB = sWb + (fq * 32 + r) * WP + cc;
#pragma unroll
        for (int ks = 0; ks < 8; ks++) {
            uint32_t a0 = pA[ks * 8];
            uint32_t a1 = pA[8 * WP + ks * 8];
            uint32_t a2 = pA[ks * 8 + 4];
            uint32_t a3 = pA[8 * WP + ks * 8 + 4];
#pragma unroll
            for (int nt = 0; nt < 4; nt++) {
                uint32_t bA0 = pB[nt * 8 * WP + ks * 8];
                uint32_t bA1 = pB[nt * 8 * WP + ks * 8 + 4];
                uint32_t bB0 = pB[EF * WP + nt * 8 * WP + ks * 8];
                uint32_t bB1 = pB[EF * WP + nt * 8 * WP + ks * 8 + 4];
                mma_bf16(accA[nt], a0, a1, a2, a3, bA0, bA1);
                mma_bf16(accB[nt], a0, a1, a2, a3, bB0, bB1);
            }
        }

        // ---- score phase on fragments ----
        int mA = pass ? 1 : 0;
        int mM = pass ? 3 : 2;
        float sacc[2][4];
#pragma unroll
        for (int row = 0; row < 2; row++)
#pragma unroll
            for (int it = 0; it < 4; it++) sacc[row][it] = 0.f;

#pragma unroll
        for (int nt = 0; nt < 4; nt++) {
            int c0 = fq * 32 + nt * 8 + 2 * cc;
            float2 v01 = *(const float2*)(sv + pass * EF + c0);
#pragma unroll
            for (int it = 0; it < 4; it++) {
                float2 wA = *(const float2*)(swq + it * 512 + mA * EF + c0);
                float2 wM = *(const float2*)(swq + it * 512 + mM * EF + c0);
                sacc[0][it] += v01.x * tanha(accA[nt][0] + wA.x + accB[nt][0] * wM.x)
                             + v01.y * tanha(accA[nt][1] + wA.y + accB[nt][1] * wM.y);
                sacc[1][it] += v01.x * tanha(accA[nt][2] + wA.x + accB[nt][2] * wM.x)
                             + v01.y * tanha(accA[nt][3] + wA.y + accB[nt][3] * wM.y);
            }
        }
#pragma unroll
        for (int row = 0; row < 2; row++)
#pragma unroll
            for (int it = 0; it < 4; it++) {
                float x = sacc[row][it];
                x += __shfl_xor_sync(0xffffffffu, x, 1);
                x += __shfl_xor_sync(0xffffffffu, x, 2);
                if (cc == 0) {
                    int g = gt * 16 + r + row * 8;
                    ss[((pass * 4 + fq) * GT + g) * 4 + it] = x;
                }
            }
    }
    __syncthreads();

    // ---- combine, mask, write logits ----
    if (tid < GT * 4) {
        int g = tid >> 2, it = tid & 3;
        float s = 0.f;
#pragma unroll
        for (int j = 0; j < 8; j++) s += ss[(j * GT + g) * 4 + it];
        int gg = g0 + g;
        if (gg < GSZ) {
            bool msk;
            if (it == 0) msk = (gg == sS.last_action);
            else {
                int j = it - 1;
                int d = svt[g];
                msk = (d <= sS.vtt_a[j]);
                if (j == 0) msk = msk || (d > GSZ - 2);
                if (sS.stopped[j] && gg == sS.act[j]) msk = false;
                if (sS.allow[j] && gg == sS.ai0) msk = false;
            }
            g_L[((size_t)(b * KM + it)) * GSZ + gg] = msk ? NEGV : tanhf(s) * 10.0f;
        }
    }
}

// ---------------- kernel D: log-softmax + ll ----------------------------------
__global__ void kD(float* __restrict__ out) {
    int b = blockIdx.x;
    int tid = threadIdx.x;
    __shared__ float red[256];
    __shared__ Scal sS;
    if (tid == 0) sS = g_scal[b];
    __syncthreads();
    float ll = 0.f;
    for (int it = 0; it < KM; it++) {
        const float* Lp = g_L + ((size_t)(b * KM + it)) * GSZ;
        float mx = -3.4e38f;
        for (int gi = tid; gi < GSZ; gi += 256) mx = fmaxf(mx, Lp[gi]);
        red[tid] = mx;
        __syncthreads();
        for (int st = 128; st >= 1; st >>= 1) {
            if (tid < st) red[tid] = fmaxf(red[tid], red[tid + st]);
            __syncthreads();
        }
        mx = red[0];
        __syncthreads();
        float se = 0.f;
        for (int gi = tid; gi < GSZ; gi += 256) se += expf(Lp[gi] - mx);
        red[tid] = se;
        __syncthreads();
        for (int st = 128; st >= 1; st >>= 1) {
            if (tid < st) red[tid] += red[tid + st];
            __syncthreads();
        }
        if (tid == 0) {
            float lse = mx + logf(red[0]);
            float loss = Lp[sS.act[it]] - lse;
            if (it == 0) ll += loss;
            else if (!sS.stopped[it - 1]) ll += loss;
        }
        __syncthreads();
    }
    if (tid == 0) out[BSZ * 12 + b] = ll;
}

// ---------------- launch ------------------------------------------------------
extern "C" void kernel_launch(void* const* d_in, const int* in_sizes, int n_in,
                              void* d_out, int out_size) {
    const float* h   = (const float*)d_in[0];
    const int*   rec = (const int*)d_in[1];
    const int*   vt  = (const int*)d_in[3];
    const int*   la  = (const int*)d_in[4];
    const int*   fa  = (const int*)d_in[5];
    const float* Wk1 = (const float*)d_in[6];
    const float* Wk2 = (const float*)d_in[7];
    const float* Wk3 = (const float*)d_in[8];
    const float* Wk4 = (const float*)d_in[9];
    const float* WQ1 = (const float*)d_in[10];
    const float* WQ2 = (const float*)d_in[11];
    const float* WQ3 = (const float*)d_in[12];
    const float* WQ4 = (const float*)d_in[13];

    const float *Winit, *binit, *V1, *V2, *initq;
    int base;
    if (in_sizes[14] == EF * EF) {
        Winit = (const float*)d_in[14];
        binit = (const float*)d_in[15];
        V1    = (const float*)d_in[16];
        V2    = (const float*)d_in[17];
        initq = (const float*)d_in[18];
        base = 19;
    } else {
        V1    = (const float*)d_in[14];
        V2    = (const float*)d_in[15];
        Winit = (const float*)d_in[16];
        binit = (const float*)d_in[17];
        initq = (const float*)d_in[18];
        base = 19;
    }
    const float* W1ih = (const float*)d_in[base + 0];
    const float* W1hh = (const float*)d_in[base + 1];
    const float* b1ih = (const float*)d_in[base + 2];
    const float* b1hh = (const float*)d_in[base + 3];
    const float* W2ih = (const float*)d_in[base + 4];
    const float* W2hh = (const float*)d_in[base + 5];
    const float* b2ih = (const float*)d_in[base + 6];
    const float* b2hh = (const float*)d_in[base + 7];

    float* out = (float*)d_out;

    cudaFuncSetAttribute(kC, cudaFuncAttributeMaxDynamicSharedMemorySize, KC_SMEM);

    kA<<<1, 128>>>(rec, vt, la, fa, out);
    kPw<<<2, 512>>>(Wk1, Wk2, Wk3, Wk4);
    kB0<<<dim3(4, BSZ), 256>>>(h);
    kB<<<BSZ, 512>>>(h, Winit, binit, initq,
                     W1ih, W1hh, b1ih, b1hh, W2ih, W2hh, b2ih, b2hh,
                     WQ1, WQ2, WQ3, WQ4);
    kC<<<dim3((GSZ + GT - 1) / GT, BSZ), 512, KC_SMEM>>>(h, vt, V1, V2);
    kD<<<BSZ, 256>>>(out);
}